// round 1
// baseline (speedup 1.0000x reference)
#include <cuda_runtime.h>

#define FULLMASK 0xffffffffu

constexpr int S_LEN = 192;
constexpr int M_ROWS = 128 * 192;   // 24576
constexpr int NWARPS = 12;
constexpr int NTHREADS = NWARPS * 32;
constexpr int NGROUPS = M_ROWS / 4; // 6144

// ---- shared memory layout (float offsets) ----
constexpr int OFF_W1  = 0;          // [64][256]
constexpr int OFF_W2  = 16384;      // [256][64]
constexpr int OFF_WO  = 32768;      // [64][64]
constexpr int OFF_WE  = 36864;      // [2][64]
constexpr int OFF_BE  = 36992;      // [64]
constexpr int OFF_WEQ = 37056;      // [2][64]
constexpr int OFF_WEK = 37184;      // [2][64]
constexpr int OFF_WEV = 37312;      // [2][64]
constexpr int OFF_BEQ = 37440;
constexpr int OFF_BEK = 37504;
constexpr int OFF_BEV = 37568;
constexpr int OFF_BO  = 37632;
constexpr int OFF_B1  = 37696;      // [256]
constexpr int OFF_B2  = 37952;
constexpr int OFF_G1  = 38016;
constexpr int OFF_LB1 = 38080;
constexpr int OFF_G2  = 38144;
constexpr int OFF_LB2 = 38208;
constexpr int OFF_SCR = 38272;      // per-warp scratch, 1280 floats each
constexpr int SCR_PER_WARP = 1280;  // [0,256) = x rows, [256,1280) = h rows (also oh)
constexpr int SMEM_FLOATS = OFF_SCR + NWARPS * SCR_PER_WARP; // 53632 -> 214528 B

// combined weights (computed by setup kernel each launch)
__device__ float g_WeQ[128];
__device__ float g_WeK[128];
__device__ float g_WeV[128];
__device__ float g_beQ[64];
__device__ float g_beK[64];
__device__ float g_beV[64];

__global__ void setup_kernel(const float* __restrict__ We, const float* __restrict__ be,
                             const float* __restrict__ Wq, const float* __restrict__ Wk,
                             const float* __restrict__ Wv) {
    int j = threadIdx.x;            // 0..63, j = h*16 + d
    int h = j >> 4, d = j & 15;
    float q0 = 0.f, q1 = 0.f, k0 = 0.f, k1 = 0.f, v0 = 0.f, v1 = 0.f;
    float bq = 0.f, bk = 0.f, bv = 0.f;
    for (int e = 0; e < 16; e++) {
        float we0 = We[h * 16 + e];
        float we1 = We[64 + h * 16 + e];
        float bb  = be[h * 16 + e];
        float wq = Wq[e * 16 + d];
        float wk = Wk[e * 16 + d];
        float wv = Wv[e * 16 + d];
        q0 = fmaf(we0, wq, q0); q1 = fmaf(we1, wq, q1); bq = fmaf(bb, wq, bq);
        k0 = fmaf(we0, wk, k0); k1 = fmaf(we1, wk, k1); bk = fmaf(bb, wk, bk);
        v0 = fmaf(we0, wv, v0); v1 = fmaf(we1, wv, v1); bv = fmaf(bb, wv, bv);
    }
    g_WeQ[j] = q0; g_WeQ[64 + j] = q1; g_beQ[j] = bq;
    g_WeK[j] = k0; g_WeK[64 + j] = k1; g_beK[j] = bk;
    g_WeV[j] = v0; g_WeV[64 + j] = v1; g_beV[j] = bv;
}

__device__ __forceinline__ float warp_bcast(float v, int src) {
    return __shfl_sync(FULLMASK, v, src);
}

__global__ void __launch_bounds__(NTHREADS, 1)
main_kernel(const float* __restrict__ prec, const int* __restrict__ topmask,
            const float* __restrict__ We, const float* __restrict__ be,
            const float* __restrict__ Wo, const float* __restrict__ bo,
            const float* __restrict__ g1, const float* __restrict__ lb1,
            const float* __restrict__ W1, const float* __restrict__ b1,
            const float* __restrict__ W2, const float* __restrict__ b2,
            const float* __restrict__ g2, const float* __restrict__ lb2,
            float* __restrict__ out)
{
    extern __shared__ float sm[];
    const int tid = threadIdx.x;

    // ---- cooperative weight staging ----
    {
        float4* d = (float4*)(sm + OFF_W1);
        const float4* s = (const float4*)W1;
        for (int i = tid; i < 16384 / 4; i += NTHREADS) d[i] = s[i];
        d = (float4*)(sm + OFF_W2); s = (const float4*)W2;
        for (int i = tid; i < 16384 / 4; i += NTHREADS) d[i] = s[i];
        d = (float4*)(sm + OFF_WO); s = (const float4*)Wo;
        for (int i = tid; i < 4096 / 4; i += NTHREADS) d[i] = s[i];
    }
    if (tid < 128) {
        sm[OFF_WE + tid]  = We[tid];
        sm[OFF_WEQ + tid] = g_WeQ[tid];
        sm[OFF_WEK + tid] = g_WeK[tid];
        sm[OFF_WEV + tid] = g_WeV[tid];
    }
    if (tid < 64) {
        sm[OFF_BE + tid]  = be[tid];
        sm[OFF_BEQ + tid] = g_beQ[tid];
        sm[OFF_BEK + tid] = g_beK[tid];
        sm[OFF_BEV + tid] = g_beV[tid];
        sm[OFF_BO + tid]  = bo[tid];
        sm[OFF_B2 + tid]  = b2[tid];
        sm[OFF_G1 + tid]  = g1[tid];
        sm[OFF_LB1 + tid] = lb1[tid];
        sm[OFF_G2 + tid]  = g2[tid];
        sm[OFF_LB2 + tid] = lb2[tid];
    }
    if (tid < 256) sm[OFF_B1 + tid] = b1[tid];
    __syncthreads();

    const int warp = tid >> 5;
    const int L = tid & 31;
    const int gw = blockIdx.x * NWARPS + warp;
    const int nW = gridDim.x * NWARPS;
    float* sx  = sm + OFF_SCR + warp * SCR_PER_WARP;   // 256 floats: 4 rows x 64 (x)
    float* sh  = sx + 256;                             // 1024 floats: 4 rows x 256 (h / oh)

    for (int g = gw; g < NGROUPS; g += nW) {
        const int m0 = g * 4;
        float qres_lo[4], qres_hi[4];

        // ================= Phase A: attention per row =================
        #pragma unroll
        for (int r = 0; r < 4; r++) {
            const int m = m0 + r;
            const int bb = m / S_LEN;
            const int ss = m - bb * S_LEN;
            const int kq = ss & 31;
            const float2 pk = ((const float2*)prec)[m * 32 + L];
            const int mk = topmask[bb * 32 + L];

            const float pq0 = warp_bcast(pk.x, kq);
            const float pq1 = warp_bcast(pk.y, kq);

            qres_lo[r] = fmaf(pq0, sm[OFF_WE + L],      fmaf(pq1, sm[OFF_WE + 64 + L],      sm[OFF_BE + L]));
            qres_hi[r] = fmaf(pq0, sm[OFF_WE + 32 + L], fmaf(pq1, sm[OFF_WE + 96 + L],      sm[OFF_BE + 32 + L]));
            const float qhl = fmaf(pq0, sm[OFF_WEQ + L],      fmaf(pq1, sm[OFF_WEQ + 64 + L], sm[OFF_BEQ + L]));
            const float qhh = fmaf(pq0, sm[OFF_WEQ + 32 + L], fmaf(pq1, sm[OFF_WEQ + 96 + L], sm[OFF_BEQ + 32 + L]));

            float tal = qhl * sm[OFF_WEK + L],      tah = qhh * sm[OFF_WEK + 32 + L];
            float tbl = qhl * sm[OFF_WEK + 64 + L], tbh = qhh * sm[OFF_WEK + 96 + L];
            float tcl = qhl * sm[OFF_BEK + L],      tch = qhh * sm[OFF_BEK + 32 + L];
            #pragma unroll
            for (int o = 1; o <= 8; o <<= 1) {
                tal += __shfl_xor_sync(FULLMASK, tal, o);
                tah += __shfl_xor_sync(FULLMASK, tah, o);
                tbl += __shfl_xor_sync(FULLMASK, tbl, o);
                tbh += __shfl_xor_sync(FULLMASK, tbh, o);
                tcl += __shfl_xor_sync(FULLMASK, tcl, o);
                tch += __shfl_xor_sync(FULLMASK, tch, o);
            }
            const float A0 = warp_bcast(tal, 0), A1 = warp_bcast(tal, 16);
            const float A2 = warp_bcast(tah, 0), A3 = warp_bcast(tah, 16);
            const float B0 = warp_bcast(tbl, 0), B1 = warp_bcast(tbl, 16);
            const float B2 = warp_bcast(tbh, 0), B3 = warp_bcast(tbh, 16);
            const float C0 = warp_bcast(tcl, 0), C1 = warp_bcast(tcl, 16);
            const float C2 = warp_bcast(tch, 0), C3 = warp_bcast(tch, 16);

            float e0 = fmaf(A0, pk.x, fmaf(B0, pk.y, C0));
            float e1 = fmaf(A1, pk.x, fmaf(B1, pk.y, C1));
            float e2 = fmaf(A2, pk.x, fmaf(B2, pk.y, C2));
            float e3 = fmaf(A3, pk.x, fmaf(B3, pk.y, C3));
            if (mk == 0) { e0 = -1e20f; e1 = -1e20f; e2 = -1e20f; e3 = -1e20f; }
            e0 *= 0.125f; e1 *= 0.125f; e2 *= 0.125f; e3 *= 0.125f;

            float x0 = e0, x1 = e1, x2 = e2, x3 = e3;
            #pragma unroll
            for (int o = 16; o >= 1; o >>= 1) {
                x0 = fmaxf(x0, __shfl_xor_sync(FULLMASK, x0, o));
                x1 = fmaxf(x1, __shfl_xor_sync(FULLMASK, x1, o));
                x2 = fmaxf(x2, __shfl_xor_sync(FULLMASK, x2, o));
                x3 = fmaxf(x3, __shfl_xor_sync(FULLMASK, x3, o));
            }
            float p0 = __expf(e0 - x0), p1 = __expf(e1 - x1);
            float p2 = __expf(e2 - x2), p3 = __expf(e3 - x3);
            float u0 = p0 * pk.x, u1 = p1 * pk.x, u2 = p2 * pk.x, u3 = p3 * pk.x;
            float v0 = p0 * pk.y, v1 = p1 * pk.y, v2 = p2 * pk.y, v3 = p3 * pk.y;
            float s0 = p0, s1 = p1, s2 = p2, s3 = p3;
            #pragma unroll
            for (int o = 16; o >= 1; o >>= 1) {
                s0 += __shfl_xor_sync(FULLMASK, s0, o);
                s1 += __shfl_xor_sync(FULLMASK, s1, o);
                s2 += __shfl_xor_sync(FULLMASK, s2, o);
                s3 += __shfl_xor_sync(FULLMASK, s3, o);
                u0 += __shfl_xor_sync(FULLMASK, u0, o);
                u1 += __shfl_xor_sync(FULLMASK, u1, o);
                u2 += __shfl_xor_sync(FULLMASK, u2, o);
                u3 += __shfl_xor_sync(FULLMASK, u3, o);
                v0 += __shfl_xor_sync(FULLMASK, v0, o);
                v1 += __shfl_xor_sync(FULLMASK, v1, o);
                v2 += __shfl_xor_sync(FULLMASK, v2, o);
                v3 += __shfl_xor_sync(FULLMASK, v3, o);
            }
            const float i0 = 1.0f / s0, i1 = 1.0f / s1, i2 = 1.0f / s2, i3 = 1.0f / s3;
            const float S0l = (L < 16) ? u0 * i0 : u1 * i1;
            const float S1l = (L < 16) ? v0 * i0 : v1 * i1;
            const float S0h = (L < 16) ? u2 * i2 : u3 * i3;
            const float S1h = (L < 16) ? v2 * i2 : v3 * i3;

            const float ohl = fmaf(S0l, sm[OFF_WEV + L],      fmaf(S1l, sm[OFF_WEV + 64 + L], sm[OFF_BEV + L]));
            const float ohh = fmaf(S0h, sm[OFF_WEV + 32 + L], fmaf(S1h, sm[OFF_WEV + 96 + L], sm[OFF_BEV + 32 + L]));
            sh[r * 64 + L] = ohl;
            sh[r * 64 + 32 + L] = ohh;
        }
        __syncwarp();

        // ================= Phase B: ao = oh @ Wo + bo =================
        float ao_lo[4], ao_hi[4];
        #pragma unroll
        for (int r = 0; r < 4; r++) { ao_lo[r] = sm[OFF_BO + L]; ao_hi[r] = sm[OFF_BO + 32 + L]; }
        #pragma unroll 4
        for (int iq = 0; iq < 16; iq++) {
            float ov[4][4];
            #pragma unroll
            for (int r = 0; r < 4; r++) {
                float4 t = *(const float4*)&sh[r * 64 + iq * 4];
                ov[r][0] = t.x; ov[r][1] = t.y; ov[r][2] = t.z; ov[r][3] = t.w;
            }
            #pragma unroll
            for (int c = 0; c < 4; c++) {
                const int i = iq * 4 + c;
                const float woa = sm[OFF_WO + i * 64 + L];
                const float wob = sm[OFF_WO + i * 64 + 32 + L];
                #pragma unroll
                for (int r = 0; r < 4; r++) {
                    ao_lo[r] = fmaf(ov[r][c], woa, ao_lo[r]);
                    ao_hi[r] = fmaf(ov[r][c], wob, ao_hi[r]);
                }
            }
        }

        // ================= LN1 -> x =================
        float x_lo[4], x_hi[4];
        #pragma unroll
        for (int r = 0; r < 4; r++) {
            float vl = ao_lo[r] + qres_lo[r];
            float vh = ao_hi[r] + qres_hi[r];
            float s = vl + vh;
            #pragma unroll
            for (int o = 16; o >= 1; o >>= 1) s += __shfl_xor_sync(FULLMASK, s, o);
            const float mu = s * (1.0f / 64.0f);
            const float dl = vl - mu, dh = vh - mu;
            float q = fmaf(dl, dl, dh * dh);
            #pragma unroll
            for (int o = 16; o >= 1; o >>= 1) q += __shfl_xor_sync(FULLMASK, q, o);
            const float rs = rsqrtf(fmaf(q, 1.0f / 64.0f, 1e-5f));
            x_lo[r] = fmaf(dl * rs, sm[OFF_G1 + L],      sm[OFF_LB1 + L]);
            x_hi[r] = fmaf(dh * rs, sm[OFF_G1 + 32 + L], sm[OFF_LB1 + 32 + L]);
            sx[r * 64 + L] = x_lo[r];
            sx[r * 64 + 32 + L] = x_hi[r];
        }
        __syncwarp();

        // ================= Phase C: h = relu(x @ W1 + b1) =================
        float acc[4][8];
        {
            const float4 ba = *(const float4*)&sm[OFF_B1 + 8 * L];
            const float4 bb = *(const float4*)&sm[OFF_B1 + 8 * L + 4];
            #pragma unroll
            for (int r = 0; r < 4; r++) {
                acc[r][0] = ba.x; acc[r][1] = ba.y; acc[r][2] = ba.z; acc[r][3] = ba.w;
                acc[r][4] = bb.x; acc[r][5] = bb.y; acc[r][6] = bb.z; acc[r][7] = bb.w;
            }
        }
        #pragma unroll 4
        for (int jq = 0; jq < 16; jq++) {
            float xv[4][4];
            #pragma unroll
            for (int r = 0; r < 4; r++) {
                float4 t = *(const float4*)&sx[r * 64 + jq * 4];
                xv[r][0] = t.x; xv[r][1] = t.y; xv[r][2] = t.z; xv[r][3] = t.w;
            }
            #pragma unroll
            for (int c = 0; c < 4; c++) {
                const int j = jq * 4 + c;
                const float4 wa = *(const float4*)&sm[OFF_W1 + j * 256 + 8 * L];
                const float4 wb = *(const float4*)&sm[OFF_W1 + j * 256 + 8 * L + 4];
                #pragma unroll
                for (int r = 0; r < 4; r++) {
                    const float xc = xv[r][c];
                    acc[r][0] = fmaf(xc, wa.x, acc[r][0]);
                    acc[r][1] = fmaf(xc, wa.y, acc[r][1]);
                    acc[r][2] = fmaf(xc, wa.z, acc[r][2]);
                    acc[r][3] = fmaf(xc, wa.w, acc[r][3]);
                    acc[r][4] = fmaf(xc, wb.x, acc[r][4]);
                    acc[r][5] = fmaf(xc, wb.y, acc[r][5]);
                    acc[r][6] = fmaf(xc, wb.z, acc[r][6]);
                    acc[r][7] = fmaf(xc, wb.w, acc[r][7]);
                }
            }
        }
        #pragma unroll
        for (int r = 0; r < 4; r++) {
            #pragma unroll
            for (int t = 0; t < 8; t++) acc[r][t] = fmaxf(acc[r][t], 0.0f);
            *(float4*)&sh[r * 256 + 8 * L]     = make_float4(acc[r][0], acc[r][1], acc[r][2], acc[r][3]);
            *(float4*)&sh[r * 256 + 8 * L + 4] = make_float4(acc[r][4], acc[r][5], acc[r][6], acc[r][7]);
        }
        __syncwarp();

        // ================= Phase D: y = h @ W2 + b2 =================
        float y_lo[4], y_hi[4];
        #pragma unroll
        for (int r = 0; r < 4; r++) { y_lo[r] = sm[OFF_B2 + L]; y_hi[r] = sm[OFF_B2 + 32 + L]; }
        #pragma unroll 4
        for (int qq = 0; qq < 64; qq++) {
            float hv[4][4];
            #pragma unroll
            for (int r = 0; r < 4; r++) {
                float4 t = *(const float4*)&sh[r * 256 + qq * 4];
                hv[r][0] = t.x; hv[r][1] = t.y; hv[r][2] = t.z; hv[r][3] = t.w;
            }
            #pragma unroll
            for (int c = 0; c < 4; c++) {
                const int jj = qq * 4 + c;
                const float w2a = sm[OFF_W2 + jj * 64 + L];
                const float w2b = sm[OFF_W2 + jj * 64 + 32 + L];
                #pragma unroll
                for (int r = 0; r < 4; r++) {
                    y_lo[r] = fmaf(hv[r][c], w2a, y_lo[r]);
                    y_hi[r] = fmaf(hv[r][c], w2b, y_hi[r]);
                }
            }
        }

        // ================= LN2 + store =================
        #pragma unroll
        for (int r = 0; r < 4; r++) {
            float vl = y_lo[r] + x_lo[r];
            float vh = y_hi[r] + x_hi[r];
            float s = vl + vh;
            #pragma unroll
            for (int o = 16; o >= 1; o >>= 1) s += __shfl_xor_sync(FULLMASK, s, o);
            const float mu = s * (1.0f / 64.0f);
            const float dl = vl - mu, dh = vh - mu;
            float q = fmaf(dl, dl, dh * dh);
            #pragma unroll
            for (int o = 16; o >= 1; o >>= 1) q += __shfl_xor_sync(FULLMASK, q, o);
            const float rs = rsqrtf(fmaf(q, 1.0f / 64.0f, 1e-5f));
            out[(m0 + r) * 64 + L]      = fmaf(dl * rs, sm[OFF_G2 + L],      sm[OFF_LB2 + L]);
            out[(m0 + r) * 64 + 32 + L] = fmaf(dh * rs, sm[OFF_G2 + 32 + L], sm[OFF_LB2 + 32 + L]);
        }
        __syncwarp();
    }
}

extern "C" void kernel_launch(void* const* d_in, const int* in_sizes, int n_in,
                              void* d_out, int out_size) {
    const float* prec = (const float*)d_in[0];
    const int*   msk  = (const int*)d_in[1];
    const float* We   = (const float*)d_in[2];
    const float* be   = (const float*)d_in[3];
    const float* Wq   = (const float*)d_in[4];
    const float* Wk   = (const float*)d_in[5];
    const float* Wv   = (const float*)d_in[6];
    const float* Wo   = (const float*)d_in[7];
    const float* bo   = (const float*)d_in[8];
    const float* g1   = (const float*)d_in[9];
    const float* lb1  = (const float*)d_in[10];
    const float* W1   = (const float*)d_in[11];
    const float* b1   = (const float*)d_in[12];
    const float* W2   = (const float*)d_in[13];
    const float* b2   = (const float*)d_in[14];
    const float* g2   = (const float*)d_in[15];
    const float* lb2  = (const float*)d_in[16];
    float* out = (float*)d_out;

    const int smem_bytes = SMEM_FLOATS * (int)sizeof(float);
    cudaFuncSetAttribute(main_kernel, cudaFuncAttributeMaxDynamicSharedMemorySize, smem_bytes);

    int nsm = 148;
    cudaDeviceGetAttribute(&nsm, cudaDevAttrMultiProcessorCount, 0);

    setup_kernel<<<1, 64>>>(We, be, Wq, Wk, Wv);
    main_kernel<<<nsm, NTHREADS, smem_bytes>>>(prec, msk, We, be, Wo, bo,
                                               g1, lb1, W1, b1, W2, b2, g2, lb2, out);
}

// round 2
// speedup vs baseline: 1.4004x; 1.4004x over previous
#include <cuda_runtime.h>

typedef unsigned long long u64;
#define FULLMASK 0xffffffffu

constexpr int NWARPS   = 12;
constexpr int NTHREADS = NWARPS * 32;
constexpr int NGROUPS  = 24576 / 8;   // 3072 groups of 8 rows

// ---- shared memory layout (float offsets) ----
constexpr int OFF_W1  = 0;          // [64][256] plain
constexpr int OFF_W2P = 16384;      // float2[256][32]: (W2[j][L], W2[j][L+32])
constexpr int OFF_WOP = 32768;      // float2[64][32]:  (Wo[i][L], Wo[i][L+32])
constexpr int OFF_B1  = 36864;      // [256]
constexpr int OFF_WE  = 37120;      // [2][64]
constexpr int OFF_BE  = 37248;
constexpr int OFF_WEQ = 37312;
constexpr int OFF_BEQ = 37440;
constexpr int OFF_WEK = 37504;
constexpr int OFF_BEK = 37568;
constexpr int OFF_WEV = 37632;
constexpr int OFF_BEV = 37760;
constexpr int OFF_DUP = 37824;      // 12 dup arrays x 64 floats: bo_lo,bo_hi,g1_lo,g1_hi,lb1_lo,lb1_hi,b2_lo,b2_hi,g2_lo,g2_hi,lb2_lo,lb2_hi
constexpr int OFF_SCR = 38592;      // per-warp: u64[4][64] soh/sx (512 f) + u64[4][128] shc (1024 f)
constexpr int SCR_FLOATS = 1536;
constexpr int SMEM_FLOATS = OFF_SCR + NWARPS * SCR_FLOATS;   // 57024 -> 228096 B

// combined attention weights (setup kernel)
__device__ float g_WeQ[128];
__device__ float g_WeK[128];
__device__ float g_WeV[128];
__device__ float g_beQ[64];
__device__ float g_beK[64];
__device__ float g_beV[64];

__global__ void setup_kernel(const float* __restrict__ We, const float* __restrict__ be,
                             const float* __restrict__ Wq, const float* __restrict__ Wk,
                             const float* __restrict__ Wv) {
    int j = threadIdx.x;            // j = h*16 + d
    int h = j >> 4, d = j & 15;
    float q0 = 0.f, q1 = 0.f, k0 = 0.f, k1 = 0.f, v0 = 0.f, v1 = 0.f;
    float bq = 0.f, bk = 0.f, bv = 0.f;
    for (int e = 0; e < 16; e++) {
        float we0 = We[h * 16 + e];
        float we1 = We[64 + h * 16 + e];
        float bb  = be[h * 16 + e];
        float wq = Wq[e * 16 + d], wk = Wk[e * 16 + d], wv = Wv[e * 16 + d];
        q0 = fmaf(we0, wq, q0); q1 = fmaf(we1, wq, q1); bq = fmaf(bb, wq, bq);
        k0 = fmaf(we0, wk, k0); k1 = fmaf(we1, wk, k1); bk = fmaf(bb, wk, bk);
        v0 = fmaf(we0, wv, v0); v1 = fmaf(we1, wv, v1); bv = fmaf(bb, wv, bv);
    }
    g_WeQ[j] = q0; g_WeQ[64 + j] = q1; g_beQ[j] = bq;
    g_WeK[j] = k0; g_WeK[64 + j] = k1; g_beK[j] = bk;
    g_WeV[j] = v0; g_WeV[64 + j] = v1; g_beV[j] = bv;
}

// ---- f32x2 helpers ----
__device__ __forceinline__ u64 pk2(float lo, float hi) {
    u64 r; asm("mov.b64 %0,{%1,%2};" : "=l"(r) : "f"(lo), "f"(hi)); return r;
}
__device__ __forceinline__ u64 dup2(float v) { return pk2(v, v); }
__device__ __forceinline__ void un2(u64 v, float& a, float& b) {
    asm("mov.b64 {%0,%1},%2;" : "=f"(a), "=f"(b) : "l"(v));
}
__device__ __forceinline__ u64 f2fma(u64 a, u64 b, u64 c) {
    u64 d; asm("fma.rn.f32x2 %0,%1,%2,%3;" : "=l"(d) : "l"(a), "l"(b), "l"(c)); return d;
}
__device__ __forceinline__ u64 f2add(u64 a, u64 b) {
    u64 d; asm("add.rn.f32x2 %0,%1,%2;" : "=l"(d) : "l"(a), "l"(b)); return d;
}
__device__ __forceinline__ u64 f2mul(u64 a, u64 b) {
    u64 d; asm("mul.rn.f32x2 %0,%1,%2;" : "=l"(d) : "l"(a), "l"(b)); return d;
}
__device__ __forceinline__ u64 shflx2(u64 v, int o) {
    float a, b; un2(v, a, b);
    a = __shfl_xor_sync(FULLMASK, a, o);
    b = __shfl_xor_sync(FULLMASK, b, o);
    return pk2(a, b);
}

// layernorm on row-pairs: vlo = channels L (rows p,p+4), vhi = channels L+32
__device__ __forceinline__ void ln_pair(u64 vlo, u64 vhi, u64 glo, u64 ghi, u64 blo, u64 bhi,
                                        u64& xlo, u64& xhi) {
    u64 s = f2add(vlo, vhi);
    #pragma unroll
    for (int o = 16; o >= 1; o >>= 1) s = f2add(s, shflx2(s, o));
    u64 mun = f2mul(s, dup2(-1.0f / 64.0f));
    u64 dlo = f2add(vlo, mun), dhi = f2add(vhi, mun);
    u64 q = f2fma(dlo, dlo, f2mul(dhi, dhi));
    #pragma unroll
    for (int o = 16; o >= 1; o >>= 1) q = f2add(q, shflx2(q, o));
    float qa, qb; un2(q, qa, qb);
    float ra = rsqrtf(fmaf(qa, 1.0f / 64.0f, 1e-5f));
    float rb = rsqrtf(fmaf(qb, 1.0f / 64.0f, 1e-5f));
    u64 rs = pk2(ra, rb);
    xlo = f2fma(f2mul(dlo, rs), glo, blo);
    xhi = f2fma(f2mul(dhi, rs), ghi, bhi);
}

__global__ void __launch_bounds__(NTHREADS, 1)
main_kernel(const float* __restrict__ prec, const int* __restrict__ topmask,
            const float* __restrict__ We, const float* __restrict__ be,
            const float* __restrict__ Wo, const float* __restrict__ bo,
            const float* __restrict__ g1, const float* __restrict__ lb1,
            const float* __restrict__ W1, const float* __restrict__ b1,
            const float* __restrict__ W2, const float* __restrict__ b2,
            const float* __restrict__ g2, const float* __restrict__ lb2,
            float* __restrict__ out)
{
    extern __shared__ float sm[];
    const int tid = threadIdx.x;

    // ---- staging ----
    {
        float4* d = (float4*)(sm + OFF_W1);
        const float4* s = (const float4*)W1;
        for (int i = tid; i < 16384 / 4; i += NTHREADS) d[i] = s[i];
    }
    for (int i = tid; i < 256 * 32; i += NTHREADS) {  // W2 pairs
        int j = i >> 5, l = i & 31;
        sm[OFF_W2P + i * 2]     = W2[j * 64 + l];
        sm[OFF_W2P + i * 2 + 1] = W2[j * 64 + 32 + l];
    }
    for (int i = tid; i < 64 * 32; i += NTHREADS) {   // Wo pairs
        int j = i >> 5, l = i & 31;
        sm[OFF_WOP + i * 2]     = Wo[j * 64 + l];
        sm[OFF_WOP + i * 2 + 1] = Wo[j * 64 + 32 + l];
    }
    if (tid < 256) sm[OFF_B1 + tid] = b1[tid];
    if (tid < 128) {
        sm[OFF_WE + tid]  = We[tid];
        sm[OFF_WEQ + tid] = g_WeQ[tid];
        sm[OFF_WEK + tid] = g_WeK[tid];
        sm[OFF_WEV + tid] = g_WeV[tid];
    }
    if (tid < 64) {
        sm[OFF_BE + tid]  = be[tid];
        sm[OFF_BEQ + tid] = g_beQ[tid];
        sm[OFF_BEK + tid] = g_beK[tid];
        sm[OFF_BEV + tid] = g_beV[tid];
    }
    if (tid < 32) {
        float v;
        v = bo[tid];       sm[OFF_DUP + 0 * 64 + 2 * tid] = v; sm[OFF_DUP + 0 * 64 + 2 * tid + 1] = v;
        v = bo[32 + tid];  sm[OFF_DUP + 1 * 64 + 2 * tid] = v; sm[OFF_DUP + 1 * 64 + 2 * tid + 1] = v;
        v = g1[tid];       sm[OFF_DUP + 2 * 64 + 2 * tid] = v; sm[OFF_DUP + 2 * 64 + 2 * tid + 1] = v;
        v = g1[32 + tid];  sm[OFF_DUP + 3 * 64 + 2 * tid] = v; sm[OFF_DUP + 3 * 64 + 2 * tid + 1] = v;
        v = lb1[tid];      sm[OFF_DUP + 4 * 64 + 2 * tid] = v; sm[OFF_DUP + 4 * 64 + 2 * tid + 1] = v;
        v = lb1[32 + tid]; sm[OFF_DUP + 5 * 64 + 2 * tid] = v; sm[OFF_DUP + 5 * 64 + 2 * tid + 1] = v;
        v = b2[tid];       sm[OFF_DUP + 6 * 64 + 2 * tid] = v; sm[OFF_DUP + 6 * 64 + 2 * tid + 1] = v;
        v = b2[32 + tid];  sm[OFF_DUP + 7 * 64 + 2 * tid] = v; sm[OFF_DUP + 7 * 64 + 2 * tid + 1] = v;
        v = g2[tid];       sm[OFF_DUP + 8 * 64 + 2 * tid] = v; sm[OFF_DUP + 8 * 64 + 2 * tid + 1] = v;
        v = g2[32 + tid];  sm[OFF_DUP + 9 * 64 + 2 * tid] = v; sm[OFF_DUP + 9 * 64 + 2 * tid + 1] = v;
        v = lb2[tid];      sm[OFF_DUP + 10 * 64 + 2 * tid] = v; sm[OFF_DUP + 10 * 64 + 2 * tid + 1] = v;
        v = lb2[32 + tid]; sm[OFF_DUP + 11 * 64 + 2 * tid] = v; sm[OFF_DUP + 11 * 64 + 2 * tid + 1] = v;
    }
    __syncthreads();

    const int warp = tid >> 5;
    const int L = tid & 31;
    float* scr = sm + OFF_SCR + warp * SCR_FLOATS;
    u64* sohp = (u64*)scr;           // [4][64]  oh pairs / x pairs (aliased)
    u64* shp  = sohp + 256;          // [4][128] h chunk pairs

    // hoisted attention vectors (loop invariant)
    const float we0l = sm[OFF_WE + L],      we1l = sm[OFF_WE + 64 + L];
    const float we0h = sm[OFF_WE + 32 + L], we1h = sm[OFF_WE + 96 + L];
    const float bel  = sm[OFF_BE + L],      beh  = sm[OFF_BE + 32 + L];
    const float wq0l = sm[OFF_WEQ + L],      wq1l = sm[OFF_WEQ + 64 + L];
    const float wq0h = sm[OFF_WEQ + 32 + L], wq1h = sm[OFF_WEQ + 96 + L];
    const float bql  = sm[OFF_BEQ + L],      bqh  = sm[OFF_BEQ + 32 + L];
    const float wk0l = sm[OFF_WEK + L],      wk1l = sm[OFF_WEK + 64 + L];
    const float wk0h = sm[OFF_WEK + 32 + L], wk1h = sm[OFF_WEK + 96 + L];
    const float bkl  = sm[OFF_BEK + L],      bkh  = sm[OFF_BEK + 32 + L];
    const float wv0l = sm[OFF_WEV + L],      wv1l = sm[OFF_WEV + 64 + L];
    const float wv0h = sm[OFF_WEV + 32 + L], wv1h = sm[OFF_WEV + 96 + L];
    const float bvl  = sm[OFF_BEV + L],      bvh  = sm[OFF_BEV + 32 + L];

    const int g0 = warp * gridDim.x + blockIdx.x;
    const int gstride = gridDim.x * NWARPS;

    for (int g = g0; g < NGROUPS; g += gstride) {
        const int m0 = g * 8;
        const int bb = m0 / 192;                 // 8 | 192: whole group in one batch row
        const int mk = topmask[bb * 32 + L];

        float2 pk[8];
        #pragma unroll
        for (int r = 0; r < 8; r++) pk[r] = ((const float2*)prec)[(m0 + r) * 32 + L];

        float qres_l[8], qres_h[8];

        // ================= Phase A: attention (scalar, per row) =================
        #pragma unroll
        for (int r = 0; r < 8; r++) {
            const int kq = (m0 + r) & 31;
            const float pq0 = __shfl_sync(FULLMASK, pk[r].x, kq);
            const float pq1 = __shfl_sync(FULLMASK, pk[r].y, kq);

            qres_l[r] = fmaf(pq0, we0l, fmaf(pq1, we1l, bel));
            qres_h[r] = fmaf(pq0, we0h, fmaf(pq1, we1h, beh));
            const float qhl = fmaf(pq0, wq0l, fmaf(pq1, wq1l, bql));
            const float qhh = fmaf(pq0, wq0h, fmaf(pq1, wq1h, bqh));

            float tal = qhl * wk0l, tah = qhh * wk0h;
            float tbl = qhl * wk1l, tbh = qhh * wk1h;
            float tcl = qhl * bkl,  tch = qhh * bkh;
            #pragma unroll
            for (int o = 1; o <= 8; o <<= 1) {
                tal += __shfl_xor_sync(FULLMASK, tal, o);
                tah += __shfl_xor_sync(FULLMASK, tah, o);
                tbl += __shfl_xor_sync(FULLMASK, tbl, o);
                tbh += __shfl_xor_sync(FULLMASK, tbh, o);
                tcl += __shfl_xor_sync(FULLMASK, tcl, o);
                tch += __shfl_xor_sync(FULLMASK, tch, o);
            }
            const float A0 = __shfl_sync(FULLMASK, tal, 0), A1 = __shfl_sync(FULLMASK, tal, 16);
            const float A2 = __shfl_sync(FULLMASK, tah, 0), A3 = __shfl_sync(FULLMASK, tah, 16);
            const float B0 = __shfl_sync(FULLMASK, tbl, 0), B1v = __shfl_sync(FULLMASK, tbl, 16);
            const float B2 = __shfl_sync(FULLMASK, tbh, 0), B3 = __shfl_sync(FULLMASK, tbh, 16);
            const float C0 = __shfl_sync(FULLMASK, tcl, 0), C1 = __shfl_sync(FULLMASK, tcl, 16);
            const float C2 = __shfl_sync(FULLMASK, tch, 0), C3 = __shfl_sync(FULLMASK, tch, 16);

            float e0 = fmaf(A0, pk[r].x, fmaf(B0,  pk[r].y, C0));
            float e1 = fmaf(A1, pk[r].x, fmaf(B1v, pk[r].y, C1));
            float e2 = fmaf(A2, pk[r].x, fmaf(B2,  pk[r].y, C2));
            float e3 = fmaf(A3, pk[r].x, fmaf(B3,  pk[r].y, C3));
            if (mk == 0) { e0 = -1e20f; e1 = -1e20f; e2 = -1e20f; e3 = -1e20f; }
            e0 *= 0.125f; e1 *= 0.125f; e2 *= 0.125f; e3 *= 0.125f;

            float x0 = e0, x1 = e1, x2 = e2, x3 = e3;
            #pragma unroll
            for (int o = 16; o >= 1; o >>= 1) {
                x0 = fmaxf(x0, __shfl_xor_sync(FULLMASK, x0, o));
                x1 = fmaxf(x1, __shfl_xor_sync(FULLMASK, x1, o));
                x2 = fmaxf(x2, __shfl_xor_sync(FULLMASK, x2, o));
                x3 = fmaxf(x3, __shfl_xor_sync(FULLMASK, x3, o));
            }
            float p0 = __expf(e0 - x0), p1 = __expf(e1 - x1);
            float p2 = __expf(e2 - x2), p3 = __expf(e3 - x3);
            float u0 = p0 * pk[r].x, u1 = p1 * pk[r].x, u2 = p2 * pk[r].x, u3 = p3 * pk[r].x;
            float v0 = p0 * pk[r].y, v1 = p1 * pk[r].y, v2 = p2 * pk[r].y, v3 = p3 * pk[r].y;
            float s0 = p0, s1 = p1, s2 = p2, s3 = p3;
            #pragma unroll
            for (int o = 16; o >= 1; o >>= 1) {
                s0 += __shfl_xor_sync(FULLMASK, s0, o);
                s1 += __shfl_xor_sync(FULLMASK, s1, o);
                s2 += __shfl_xor_sync(FULLMASK, s2, o);
                s3 += __shfl_xor_sync(FULLMASK, s3, o);
                u0 += __shfl_xor_sync(FULLMASK, u0, o);
                u1 += __shfl_xor_sync(FULLMASK, u1, o);
                u2 += __shfl_xor_sync(FULLMASK, u2, o);
                u3 += __shfl_xor_sync(FULLMASK, u3, o);
                v0 += __shfl_xor_sync(FULLMASK, v0, o);
                v1 += __shfl_xor_sync(FULLMASK, v1, o);
                v2 += __shfl_xor_sync(FULLMASK, v2, o);
                v3 += __shfl_xor_sync(FULLMASK, v3, o);
            }
            const float i0 = 1.0f / s0, i1 = 1.0f / s1, i2 = 1.0f / s2, i3 = 1.0f / s3;
            const float S0l = (L < 16) ? u0 * i0 : u1 * i1;
            const float S1l = (L < 16) ? v0 * i0 : v1 * i1;
            const float S0h = (L < 16) ? u2 * i2 : u3 * i3;
            const float S1h = (L < 16) ? v2 * i2 : v3 * i3;

            const float ohl = fmaf(S0l, wv0l, fmaf(S1l, wv1l, bvl));
            const float ohh = fmaf(S0h, wv0h, fmaf(S1h, wv1h, bvh));
            // store into row-pair slots: pair p = r&3, half = r>>2
            scr[(((r & 3) * 64) + L) * 2 + (r >> 2)]      = ohl;
            scr[(((r & 3) * 64) + 32 + L) * 2 + (r >> 2)] = ohh;
        }
        __syncwarp();

        // ================= Phase B: ao = oh @ Wo + bo (row-pair f32x2) =================
        u64 ao_lo[4], ao_hi[4];
        {
            u64 bol = *(const u64*)&sm[OFF_DUP + 0 * 64 + 2 * L];
            u64 boh = *(const u64*)&sm[OFF_DUP + 1 * 64 + 2 * L];
            #pragma unroll
            for (int p = 0; p < 4; p++) { ao_lo[p] = bol; ao_hi[p] = boh; }
        }
        #pragma unroll 4
        for (int i2 = 0; i2 < 32; i2++) {
            const int i = 2 * i2;
            u64 w0 = *(const u64*)&sm[OFF_WOP + (i * 32 + L) * 2];
            u64 w1 = *(const u64*)&sm[OFF_WOP + ((i + 1) * 32 + L) * 2];
            float w0l, w0h, w1l, w1h; un2(w0, w0l, w0h); un2(w1, w1l, w1h);
            const u64 w0l2 = dup2(w0l), w0h2 = dup2(w0h), w1l2 = dup2(w1l), w1h2 = dup2(w1h);
            #pragma unroll
            for (int p = 0; p < 4; p++) {
                ulonglong2 oh2 = *(const ulonglong2*)&sohp[p * 64 + i];
                ao_lo[p] = f2fma(oh2.x, w0l2, ao_lo[p]);
                ao_hi[p] = f2fma(oh2.x, w0h2, ao_hi[p]);
                ao_lo[p] = f2fma(oh2.y, w1l2, ao_lo[p]);
                ao_hi[p] = f2fma(oh2.y, w1h2, ao_hi[p]);
            }
        }

        // ================= LN1 -> x (pairs) =================
        u64 x_lo[4], x_hi[4];
        {
            const u64 g1l = *(const u64*)&sm[OFF_DUP + 2 * 64 + 2 * L];
            const u64 g1h = *(const u64*)&sm[OFF_DUP + 3 * 64 + 2 * L];
            const u64 l1l = *(const u64*)&sm[OFF_DUP + 4 * 64 + 2 * L];
            const u64 l1h = *(const u64*)&sm[OFF_DUP + 5 * 64 + 2 * L];
            #pragma unroll
            for (int p = 0; p < 4; p++) {
                u64 vlo = f2add(ao_lo[p], pk2(qres_l[p], qres_l[p + 4]));
                u64 vhi = f2add(ao_hi[p], pk2(qres_h[p], qres_h[p + 4]));
                ln_pair(vlo, vhi, g1l, g1h, l1l, l1h, x_lo[p], x_hi[p]);
            }
        }
        __syncwarp();
        #pragma unroll
        for (int p = 0; p < 4; p++) {
            sohp[p * 64 + L]      = x_lo[p];
            sohp[p * 64 + 32 + L] = x_hi[p];
        }
        __syncwarp();

        // ================= FFN: chunked C (x@W1, relu) + D (h@W2) =================
        u64 y_lo[4], y_hi[4];
        {
            u64 b2l = *(const u64*)&sm[OFF_DUP + 6 * 64 + 2 * L];
            u64 b2h = *(const u64*)&sm[OFF_DUP + 7 * 64 + 2 * L];
            #pragma unroll
            for (int p = 0; p < 4; p++) { y_lo[p] = b2l; y_hi[p] = b2h; }
        }
        #pragma unroll 1
        for (int cc = 0; cc < 2; cc++) {
            const float* W1c = sm + OFF_W1 + cc * 128 + 4 * L;
            u64 hacc[4][4];
            {
                float4 b1v = *(const float4*)&sm[OFF_B1 + cc * 128 + 4 * L];
                const u64 h0 = dup2(b1v.x), h1 = dup2(b1v.y), h2 = dup2(b1v.z), h3 = dup2(b1v.w);
                #pragma unroll
                for (int p = 0; p < 4; p++) { hacc[p][0] = h0; hacc[p][1] = h1; hacc[p][2] = h2; hacc[p][3] = h3; }
            }
            #pragma unroll 4
            for (int j = 0; j < 64; j++) {
                float4 w = *(const float4*)&W1c[j * 256];
                const u64 w0 = dup2(w.x), w1 = dup2(w.y), w2 = dup2(w.z), w3 = dup2(w.w);
                #pragma unroll
                for (int p = 0; p < 4; p++) {
                    const u64 xj = sohp[p * 64 + j];
                    hacc[p][0] = f2fma(xj, w0, hacc[p][0]);
                    hacc[p][1] = f2fma(xj, w1, hacc[p][1]);
                    hacc[p][2] = f2fma(xj, w2, hacc[p][2]);
                    hacc[p][3] = f2fma(xj, w3, hacc[p][3]);
                }
            }
            // relu + store chunk
            #pragma unroll
            for (int p = 0; p < 4; p++) {
                #pragma unroll
                for (int t = 0; t < 4; t++) {
                    float a, b; un2(hacc[p][t], a, b);
                    a = fmaxf(a, 0.0f); b = fmaxf(b, 0.0f);
                    shp[p * 128 + 4 * L + t] = pk2(a, b);
                }
            }
            __syncwarp();
            // D on this chunk
            const float* W2c = sm + OFF_W2P + cc * 128 * 64 + 2 * L;
            #pragma unroll 4
            for (int u = 0; u < 64; u++) {
                const int jj = 2 * u;
                u64 wa = *(const u64*)&W2c[jj * 64];
                u64 wb = *(const u64*)&W2c[(jj + 1) * 64];
                float wal, wah, wbl, wbh; un2(wa, wal, wah); un2(wb, wbl, wbh);
                const u64 wal2 = dup2(wal), wah2 = dup2(wah), wbl2 = dup2(wbl), wbh2 = dup2(wbh);
                #pragma unroll
                for (int p = 0; p < 4; p++) {
                    ulonglong2 h2v = *(const ulonglong2*)&shp[p * 128 + jj];
                    y_lo[p] = f2fma(h2v.x, wal2, y_lo[p]);
                    y_hi[p] = f2fma(h2v.x, wah2, y_hi[p]);
                    y_lo[p] = f2fma(h2v.y, wbl2, y_lo[p]);
                    y_hi[p] = f2fma(h2v.y, wbh2, y_hi[p]);
                }
            }
            __syncwarp();
        }

        // ================= LN2 + store =================
        {
            const u64 g2l = *(const u64*)&sm[OFF_DUP + 8 * 64 + 2 * L];
            const u64 g2h = *(const u64*)&sm[OFF_DUP + 9 * 64 + 2 * L];
            const u64 l2l = *(const u64*)&sm[OFF_DUP + 10 * 64 + 2 * L];
            const u64 l2h = *(const u64*)&sm[OFF_DUP + 11 * 64 + 2 * L];
            #pragma unroll
            for (int p = 0; p < 4; p++) {
                u64 vlo = f2add(y_lo[p], x_lo[p]);
                u64 vhi = f2add(y_hi[p], x_hi[p]);
                u64 olo, ohi;
                ln_pair(vlo, vhi, g2l, g2h, l2l, l2h, olo, ohi);
                float a, b, c, d;
                un2(olo, a, b); un2(ohi, c, d);
                out[(m0 + p) * 64 + L]           = a;
                out[(m0 + p + 4) * 64 + L]       = b;
                out[(m0 + p) * 64 + 32 + L]      = c;
                out[(m0 + p + 4) * 64 + 32 + L]  = d;
            }
        }
    }
}

extern "C" void kernel_launch(void* const* d_in, const int* in_sizes, int n_in,
                              void* d_out, int out_size) {
    const float* prec = (const float*)d_in[0];
    const int*   msk  = (const int*)d_in[1];
    const float* We   = (const float*)d_in[2];
    const float* be   = (const float*)d_in[3];
    const float* Wq   = (const float*)d_in[4];
    const float* Wk   = (const float*)d_in[5];
    const float* Wv   = (const float*)d_in[6];
    const float* Wo   = (const float*)d_in[7];
    const float* bo   = (const float*)d_in[8];
    const float* g1   = (const float*)d_in[9];
    const float* lb1  = (const float*)d_in[10];
    const float* W1   = (const float*)d_in[11];
    const float* b1   = (const float*)d_in[12];
    const float* W2   = (const float*)d_in[13];
    const float* b2   = (const float*)d_in[14];
    const float* g2   = (const float*)d_in[15];
    const float* lb2  = (const float*)d_in[16];
    float* out = (float*)d_out;

    const int smem_bytes = SMEM_FLOATS * (int)sizeof(float);
    cudaFuncSetAttribute(main_kernel, cudaFuncAttributeMaxDynamicSharedMemorySize, smem_bytes);

    int nsm = 148;
    cudaDeviceGetAttribute(&nsm, cudaDevAttrMultiProcessorCount, 0);

    setup_kernel<<<1, 64>>>(We, be, Wq, Wk, Wv);
    main_kernel<<<nsm, NTHREADS, smem_bytes>>>(prec, msk, We, be, Wo, bo,
                                               g1, lb1, W1, b1, W2, b2, g2, lb2, out);
}

// round 4
// speedup vs baseline: 1.6780x; 1.1983x over previous
#include <cuda_runtime.h>

typedef unsigned long long u64;
#define FULLMASK 0xffffffffu

constexpr int NWARPS   = 12;
constexpr int NTHREADS = NWARPS * 32;
constexpr int NGROUPS  = 24576 / 8;   // 3072 groups of 8 rows

// ---- shared memory layout (float offsets) ----
constexpr int OFF_W1  = 0;          // [64][256]
constexpr int OFF_W2  = 16384;      // [256][64]
constexpr int OFF_B1  = 32768;      // [256]
constexpr int OFF_WE  = 33024;      // [2][64]
constexpr int OFF_BE  = 33152;      // [64]
constexpr int OFF_M   = 33216;      // [4][9] bilinear energy coeffs (x 0.125*log2e), pad 40
constexpr int OFF_A0  = 33256;      // [4][64]  WeV0 @ Wo per head
constexpr int OFF_A1  = 33512;      // [4][64]
constexpr int OFF_K   = 33768;      // [64]     beV @ Wo + bo
constexpr int OFF_DUP = 33832;      // 10 x 64: g1lo,g1hi,lb1lo,lb1hi,b2lo,b2hi,g2lo,g2hi,lb2lo,lb2hi
constexpr int OFF_SCR = 34472;      // per-warp scratch (1536 floats); also setup temps pre-loop
constexpr int SCR_FLOATS = 1536;
constexpr int SMEM_FLOATS = OFF_SCR + NWARPS * SCR_FLOATS;   // 52904 -> 211616 B

// ---- f32x2 helpers ----
__device__ __forceinline__ u64 pk2(float lo, float hi) {
    u64 r; asm("mov.b64 %0,{%1,%2};" : "=l"(r) : "f"(lo), "f"(hi)); return r;
}
__device__ __forceinline__ u64 dup2(float v) { return pk2(v, v); }
__device__ __forceinline__ void un2(u64 v, float& a, float& b) {
    asm("mov.b64 {%0,%1},%2;" : "=f"(a), "=f"(b) : "l"(v));
}
__device__ __forceinline__ u64 f2fma(u64 a, u64 b, u64 c) {
    u64 d; asm("fma.rn.f32x2 %0,%1,%2,%3;" : "=l"(d) : "l"(a), "l"(b), "l"(c)); return d;
}
__device__ __forceinline__ u64 f2add(u64 a, u64 b) {
    u64 d; asm("add.rn.f32x2 %0,%1,%2;" : "=l"(d) : "l"(a), "l"(b)); return d;
}
__device__ __forceinline__ u64 f2mul(u64 a, u64 b) {
    u64 d; asm("mul.rn.f32x2 %0,%1,%2;" : "=l"(d) : "l"(a), "l"(b)); return d;
}
__device__ __forceinline__ float ex2f(float x) {
    float y; asm("ex2.approx.f32 %0,%1;" : "=f"(y) : "f"(x)); return y;
}
__device__ __forceinline__ float bfly_add(float v) {
    #pragma unroll
    for (int o = 16; o >= 1; o >>= 1) v += __shfl_xor_sync(FULLMASK, v, o);
    return v;
}

// layernorm on row-pairs: vlo = channels L (rows p,p+4), vhi = channels L+32
__device__ __forceinline__ void ln_pair(u64 vlo, u64 vhi, u64 glo, u64 ghi, u64 blo, u64 bhi,
                                        u64& xlo, u64& xhi) {
    float sa, sb; un2(f2add(vlo, vhi), sa, sb);
    sa = bfly_add(sa); sb = bfly_add(sb);
    u64 mun = f2mul(pk2(sa, sb), dup2(-1.0f / 64.0f));
    u64 dlo = f2add(vlo, mun), dhi = f2add(vhi, mun);
    float qa, qb; un2(f2fma(dlo, dlo, f2mul(dhi, dhi)), qa, qb);
    qa = bfly_add(qa); qb = bfly_add(qb);
    float ra = rsqrtf(fmaf(qa, 1.0f / 64.0f, 1e-5f));
    float rb = rsqrtf(fmaf(qb, 1.0f / 64.0f, 1e-5f));
    u64 rs = pk2(ra, rb);
    xlo = f2fma(f2mul(dlo, rs), glo, blo);
    xhi = f2fma(f2mul(dhi, rs), ghi, bhi);
}

__global__ void __launch_bounds__(NTHREADS, 1)
main_kernel(const float* __restrict__ prec, const int* __restrict__ topmask,
            const float* __restrict__ We, const float* __restrict__ be,
            const float* __restrict__ Wq, const float* __restrict__ Wk,
            const float* __restrict__ Wv, const float* __restrict__ Wo,
            const float* __restrict__ bo,
            const float* __restrict__ g1, const float* __restrict__ lb1,
            const float* __restrict__ W1, const float* __restrict__ b1,
            const float* __restrict__ W2, const float* __restrict__ b2,
            const float* __restrict__ g2, const float* __restrict__ lb2,
            float* __restrict__ out)
{
    extern __shared__ float sm[];
    const int tid = threadIdx.x;

    // ---- stage big weights (all threads) ----
    {
        float4* d = (float4*)(sm + OFF_W1);
        const float4* s = (const float4*)W1;
        for (int i = tid; i < 16384 / 4; i += NTHREADS) d[i] = s[i];
        d = (float4*)(sm + OFF_W2); s = (const float4*)W2;
        for (int i = tid; i < 16384 / 4; i += NTHREADS) d[i] = s[i];
    }
    if (tid < 256) sm[OFF_B1 + tid] = b1[tid];
    if (tid < 128) sm[OFF_WE + tid] = We[tid];
    if (tid >= 128 && tid < 192) sm[OFF_BE + tid - 128] = be[tid - 128];
    if (tid >= 192 && tid < 224) {
        int t = tid - 192;
        float v;
        v = g1[t];       sm[OFF_DUP + 0 * 64 + 2 * t] = v; sm[OFF_DUP + 0 * 64 + 2 * t + 1] = v;
        v = g1[32 + t];  sm[OFF_DUP + 1 * 64 + 2 * t] = v; sm[OFF_DUP + 1 * 64 + 2 * t + 1] = v;
        v = lb1[t];      sm[OFF_DUP + 2 * 64 + 2 * t] = v; sm[OFF_DUP + 2 * 64 + 2 * t + 1] = v;
        v = lb1[32 + t]; sm[OFF_DUP + 3 * 64 + 2 * t] = v; sm[OFF_DUP + 3 * 64 + 2 * t + 1] = v;
        v = b2[t];       sm[OFF_DUP + 4 * 64 + 2 * t] = v; sm[OFF_DUP + 4 * 64 + 2 * t + 1] = v;
        v = b2[32 + t];  sm[OFF_DUP + 5 * 64 + 2 * t] = v; sm[OFF_DUP + 5 * 64 + 2 * t + 1] = v;
        v = g2[t];       sm[OFF_DUP + 6 * 64 + 2 * t] = v; sm[OFF_DUP + 6 * 64 + 2 * t + 1] = v;
        v = g2[32 + t];  sm[OFF_DUP + 7 * 64 + 2 * t] = v; sm[OFF_DUP + 7 * 64 + 2 * t + 1] = v;
        v = lb2[t];      sm[OFF_DUP + 8 * 64 + 2 * t] = v; sm[OFF_DUP + 8 * 64 + 2 * t + 1] = v;
        v = lb2[32 + t]; sm[OFF_DUP + 9 * 64 + 2 * t] = v; sm[OFF_DUP + 9 * 64 + 2 * t + 1] = v;
    }

    // ---- setup stage 1: combined QKV embed weights into scratch temps ----
    float* tWQ = sm + OFF_SCR;         // [128]
    float* tWK = tWQ + 128;            // [128]
    float* tWV = tWK + 128;            // [128]
    float* tbQ = tWV + 128;            // [64]
    float* tbK = tbQ + 64;             // [64]
    float* tbV = tbK + 64;             // [64]
    if (tid < 64) {
        int j = tid, h = j >> 4, d = j & 15;
        float q0 = 0.f, q1 = 0.f, k0 = 0.f, k1 = 0.f, v0 = 0.f, v1 = 0.f;
        float bq = 0.f, bk = 0.f, bv = 0.f;
        for (int e = 0; e < 16; e++) {
            float we0 = We[h * 16 + e];
            float we1 = We[64 + h * 16 + e];
            float bb  = be[h * 16 + e];
            float wq = Wq[e * 16 + d], wk = Wk[e * 16 + d], wv = Wv[e * 16 + d];
            q0 = fmaf(we0, wq, q0); q1 = fmaf(we1, wq, q1); bq = fmaf(bb, wq, bq);
            k0 = fmaf(we0, wk, k0); k1 = fmaf(we1, wk, k1); bk = fmaf(bb, wk, bk);
            v0 = fmaf(we0, wv, v0); v1 = fmaf(we1, wv, v1); bv = fmaf(bb, wv, bv);
        }
        tWQ[j] = q0; tWQ[64 + j] = q1; tbQ[j] = bq;
        tWK[j] = k0; tWK[64 + j] = k1; tbK[j] = bk;
        tWV[j] = v0; tWV[64 + j] = v1; tbV[j] = bv;
    }
    __syncthreads();

    // ---- setup stage 2: bilinear energy forms + folded Wo ----
    if (tid < 4) {
        const float SC = 0.125f * 1.4426950408889634f;   // 1/sqrt(E) fold + log2e
        int hh = tid;
        float m00=0,m01=0,m02=0,m10=0,m11=0,m12=0,m20=0,m21=0,m22=0;
        for (int dd = 0; dd < 16; dd++) {
            float Q0 = tWQ[hh*16+dd], Q1 = tWQ[64+hh*16+dd], BQ = tbQ[hh*16+dd];
            float K0 = tWK[hh*16+dd], K1 = tWK[64+hh*16+dd], BK = tbK[hh*16+dd];
            m00 += Q0*K0; m01 += Q0*K1; m02 += Q0*BK;
            m10 += Q1*K0; m11 += Q1*K1; m12 += Q1*BK;
            m20 += BQ*K0; m21 += BQ*K1; m22 += BQ*BK;
        }
        sm[OFF_M+hh*9+0]=m00*SC; sm[OFF_M+hh*9+1]=m01*SC; sm[OFF_M+hh*9+2]=m02*SC;
        sm[OFF_M+hh*9+3]=m10*SC; sm[OFF_M+hh*9+4]=m11*SC; sm[OFF_M+hh*9+5]=m12*SC;
        sm[OFF_M+hh*9+6]=m20*SC; sm[OFF_M+hh*9+7]=m21*SC; sm[OFF_M+hh*9+8]=m22*SC;
    }
    if (tid >= 64 && tid < 128) {
        int j = tid - 64;
        float kk = 0.f;
        for (int hh = 0; hh < 4; hh++) {
            float s0 = 0.f, s1 = 0.f;
            for (int dd = 0; dd < 16; dd++) {
                int row = hh * 16 + dd;
                float w = Wo[row * 64 + j];
                s0 = fmaf(tWV[row], w, s0);
                s1 = fmaf(tWV[64 + row], w, s1);
                kk = fmaf(tbV[row], w, kk);
            }
            sm[OFF_A0 + hh * 64 + j] = s0;
            sm[OFF_A1 + hh * 64 + j] = s1;
        }
        sm[OFF_K + j] = kk + bo[j];
    }
    __syncthreads();

    const int warp = tid >> 5;
    const int L = tid & 31;
    float* scr = sm + OFF_SCR + warp * SCR_FLOATS;
    u64* sxp    = (u64*)scr;             // [4][64]  x pairs
    u64* shp    = sxp + 256;             // [4][128] h chunk (aliased with pkb)
    float4* pkb = (float4*)(scr + 512);  // [8][32]  (px, py, madd, 0) — aliases shp
    u64* uvb    = (u64*)scr;             // [32] (û, v̂) — aliases sxp head

    // hoisted per-lane constants
    const float we0l = sm[OFF_WE + L],      we1l = sm[OFF_WE + 64 + L],  bel = sm[OFF_BE + L];
    const float we0h = sm[OFF_WE + 32 + L], we1h = sm[OFF_WE + 96 + L], beh = sm[OFF_BE + 32 + L];
    float a0l[4], a0h[4], a1l[4], a1h[4];
    #pragma unroll
    for (int h = 0; h < 4; h++) {
        a0l[h] = sm[OFF_A0 + h * 64 + L];      a0h[h] = sm[OFF_A0 + h * 64 + 32 + L];
        a1l[h] = sm[OFF_A1 + h * 64 + L];      a1h[h] = sm[OFF_A1 + h * 64 + 32 + L];
    }
    const float kvl = sm[OFF_K + L], kvh = sm[OFF_K + 32 + L];
    const int rr = L >> 2, hh = L & 3;
    float Mh[9];
    #pragma unroll
    for (int i = 0; i < 9; i++) Mh[i] = sm[OFF_M + hh * 9 + i];

    const int g0 = warp * gridDim.x + blockIdx.x;
    const int gstride = gridDim.x * NWARPS;

    for (int g = g0; g < NGROUPS; g += gstride) {
        const int m0 = g * 8;
        const int bb = m0 / 192;             // 8 | 192: group stays in one batch row
        const int mk = topmask[bb * 32 + L];
        const float madd = (mk != 0) ? 0.0f : -4e18f;
        const int kqbase = m0 & 31;

        // ---- stage keys: (px, py, madd) per key, per row ----
        #pragma unroll
        for (int r = 0; r < 8; r++) {
            float2 p = ((const float2*)prec)[(m0 + r) * 32 + L];
            pkb[r * 32 + L] = make_float4(p.x, p.y, madd, 0.0f);
        }
        __syncwarp();

        // ---- transposed softmax: lane owns (row rr, head hh) ----
        {
            const float2 pq = *(const float2*)&pkb[rr * 32 + kqbase + rr];
            const float Ah = fmaf(pq.y, Mh[3], fmaf(pq.x, Mh[0], Mh[6]));
            const float Bh = fmaf(pq.y, Mh[4], fmaf(pq.x, Mh[1], Mh[7]));
            const float Ch = fmaf(pq.y, Mh[5], fmaf(pq.x, Mh[2], Mh[8]));
            float s = 0.f, u = 0.f, v = 0.f;
            const float4* row = &pkb[rr * 32];
            #pragma unroll 8
            for (int k = 0; k < 32; k++) {
                float4 t = row[k];
                float e = fmaf(Ah, t.x, fmaf(Bh, t.y, Ch)) + t.z;
                float p = ex2f(e);
                s += p;
                u = fmaf(p, t.x, u);
                v = fmaf(p, t.y, v);
            }
            const float inv = __fdividef(1.0f, s);
            __syncwarp();                    // pkb writes fully consumed? (still read below) — protects uvb region reuse
            uvb[L] = pk2(u * inv, v * inv);
        }
        __syncwarp();

        // ---- qres + folded attention output ao (per row, scalar) ----
        float ao_l[8], ao_h[8], qres_l[8], qres_h[8];
        #pragma unroll
        for (int r = 0; r < 8; r++) {
            const float2 pq = *(const float2*)&pkb[r * 32 + kqbase + r];
            qres_l[r] = fmaf(pq.x, we0l, fmaf(pq.y, we1l, bel));
            qres_h[r] = fmaf(pq.x, we0h, fmaf(pq.y, we1h, beh));
            float aol = kvl, aoh = kvh;
            #pragma unroll
            for (int h = 0; h < 4; h++) {
                const float2 uv = ((const float2*)uvb)[4 * r + h];
                aol = fmaf(uv.x, a0l[h], fmaf(uv.y, a1l[h], aol));
                aoh = fmaf(uv.x, a0h[h], fmaf(uv.y, a1h[h], aoh));
            }
            ao_l[r] = aol; ao_h[r] = aoh;
        }
        __syncwarp();     // all uvb/pkb reads done before x / h stores overwrite those regions

        // ---- LN1 -> x pairs ----
        u64 x_lo[4], x_hi[4];
        {
            const u64 g1l = *(const u64*)&sm[OFF_DUP + 0 * 64 + 2 * L];
            const u64 g1h = *(const u64*)&sm[OFF_DUP + 1 * 64 + 2 * L];
            const u64 l1l = *(const u64*)&sm[OFF_DUP + 2 * 64 + 2 * L];
            const u64 l1h = *(const u64*)&sm[OFF_DUP + 3 * 64 + 2 * L];
            #pragma unroll
            for (int p = 0; p < 4; p++) {
                u64 vlo = pk2(ao_l[p] + qres_l[p], ao_l[p + 4] + qres_l[p + 4]);
                u64 vhi = pk2(ao_h[p] + qres_h[p], ao_h[p + 4] + qres_h[p + 4]);
                ln_pair(vlo, vhi, g1l, g1h, l1l, l1h, x_lo[p], x_hi[p]);
            }
        }
        #pragma unroll
        for (int p = 0; p < 4; p++) {
            sxp[p * 64 + L]      = x_lo[p];
            sxp[p * 64 + 32 + L] = x_hi[p];
        }
        __syncwarp();

        // ---- Phase C: h = relu(x @ W1 + b1), all 8 owned channels in one pass ----
        u64 hacc[4][8];
        {
            const float4 b1a = *(const float4*)&sm[OFF_B1 + 4 * L];
            const float4 b1b = *(const float4*)&sm[OFF_B1 + 128 + 4 * L];
            const u64 i0 = dup2(b1a.x), i1 = dup2(b1a.y), i2 = dup2(b1a.z), i3 = dup2(b1a.w);
            const u64 i4 = dup2(b1b.x), i5 = dup2(b1b.y), i6 = dup2(b1b.z), i7 = dup2(b1b.w);
            #pragma unroll
            for (int p = 0; p < 4; p++) {
                hacc[p][0]=i0; hacc[p][1]=i1; hacc[p][2]=i2; hacc[p][3]=i3;
                hacc[p][4]=i4; hacc[p][5]=i5; hacc[p][6]=i6; hacc[p][7]=i7;
            }
        }
        #pragma unroll 4
        for (int j = 0; j < 64; j++) {
            const float4 wa = *(const float4*)&sm[OFF_W1 + j * 256 + 4 * L];
            const float4 wb = *(const float4*)&sm[OFF_W1 + j * 256 + 128 + 4 * L];
            const u64 w0 = dup2(wa.x), w1 = dup2(wa.y), w2 = dup2(wa.z), w3 = dup2(wa.w);
            const u64 w4 = dup2(wb.x), w5 = dup2(wb.y), w6 = dup2(wb.z), w7 = dup2(wb.w);
            #pragma unroll
            for (int p = 0; p < 4; p++) {
                const u64 xj = sxp[p * 64 + j];
                hacc[p][0] = f2fma(xj, w0, hacc[p][0]);
                hacc[p][1] = f2fma(xj, w1, hacc[p][1]);
                hacc[p][2] = f2fma(xj, w2, hacc[p][2]);
                hacc[p][3] = f2fma(xj, w3, hacc[p][3]);
                hacc[p][4] = f2fma(xj, w4, hacc[p][4]);
                hacc[p][5] = f2fma(xj, w5, hacc[p][5]);
                hacc[p][6] = f2fma(xj, w6, hacc[p][6]);
                hacc[p][7] = f2fma(xj, w7, hacc[p][7]);
            }
        }

        // ---- Phase D: y = h @ W2 + b2, two 128-channel chunks ----
        u64 y_lo[4], y_hi[4];
        {
            const u64 b2l = *(const u64*)&sm[OFF_DUP + 4 * 64 + 2 * L];
            const u64 b2h = *(const u64*)&sm[OFF_DUP + 5 * 64 + 2 * L];
            #pragma unroll
            for (int p = 0; p < 4; p++) { y_lo[p] = b2l; y_hi[p] = b2h; }
        }
        #pragma unroll 1
        for (int cc = 0; cc < 2; cc++) {
            #pragma unroll
            for (int p = 0; p < 4; p++) {
                #pragma unroll
                for (int t = 0; t < 4; t++) {
                    float a, b; un2(hacc[p][cc * 4 + t], a, b);
                    a = fmaxf(a, 0.0f); b = fmaxf(b, 0.0f);
                    shp[p * 128 + 4 * L + t] = pk2(a, b);
                }
            }
            __syncwarp();
            const float* W2c = sm + OFF_W2 + cc * 128 * 64;
            #pragma unroll 4
            for (int u = 0; u < 64; u++) {
                const int jj = 2 * u;
                const u64 w0l2 = dup2(W2c[jj * 64 + L]);
                const u64 w0h2 = dup2(W2c[jj * 64 + 32 + L]);
                const u64 w1l2 = dup2(W2c[(jj + 1) * 64 + L]);
                const u64 w1h2 = dup2(W2c[(jj + 1) * 64 + 32 + L]);
                #pragma unroll
                for (int p = 0; p < 4; p++) {
                    ulonglong2 h2v = *(const ulonglong2*)&shp[p * 128 + jj];
                    y_lo[p] = f2fma(h2v.x, w0l2, y_lo[p]);
                    y_hi[p] = f2fma(h2v.x, w0h2, y_hi[p]);
                    y_lo[p] = f2fma(h2v.y, w1l2, y_lo[p]);
                    y_hi[p] = f2fma(h2v.y, w1h2, y_hi[p]);
                }
            }
            __syncwarp();
        }

        // ---- LN2 + store ----
        {
            const u64 g2l = *(const u64*)&sm[OFF_DUP + 6 * 64 + 2 * L];
            const u64 g2h = *(const u64*)&sm[OFF_DUP + 7 * 64 + 2 * L];
            const u64 l2l = *(const u64*)&sm[OFF_DUP + 8 * 64 + 2 * L];
            const u64 l2h = *(const u64*)&sm[OFF_DUP + 9 * 64 + 2 * L];
            #pragma unroll
            for (int p = 0; p < 4; p++) {
                u64 vlo = f2add(y_lo[p], x_lo[p]);
                u64 vhi = f2add(y_hi[p], x_hi[p]);
                u64 olo, ohi;
                ln_pair(vlo, vhi, g2l, g2h, l2l, l2h, olo, ohi);
                float a, b, c, d;
                un2(olo, a, b); un2(ohi, c, d);
                out[(m0 + p) * 64 + L]           = a;
                out[(m0 + p + 4) * 64 + L]       = b;
                out[(m0 + p) * 64 + 32 + L]      = c;
                out[(m0 + p + 4) * 64 + 32 + L]  = d;
            }
        }
    }
}

extern "C" void kernel_launch(void* const* d_in, const int* in_sizes, int n_in,
                              void* d_out, int out_size) {
    const float* prec = (const float*)d_in[0];
    const int*   msk  = (const int*)d_in[1];
    const float* We   = (const float*)d_in[2];
    const float* be   = (const float*)d_in[3];
    const float* Wq   = (const float*)d_in[4];
    const float* Wk   = (const float*)d_in[5];
    const float* Wv   = (const float*)d_in[6];
    const float* Wo   = (const float*)d_in[7];
    const float* bo   = (const float*)d_in[8];
    const float* g1   = (const float*)d_in[9];
    const float* lb1  = (const float*)d_in[10];
    const float* W1   = (const float*)d_in[11];
    const float* b1   = (const float*)d_in[12];
    const float* W2   = (const float*)d_in[13];
    const float* b2   = (const float*)d_in[14];
    const float* g2   = (const float*)d_in[15];
    const float* lb2  = (const float*)d_in[16];
    float* out = (float*)d_out;

    const int smem_bytes = SMEM_FLOATS * (int)sizeof(float);
    cudaFuncSetAttribute(main_kernel, cudaFuncAttributeMaxDynamicSharedMemorySize, smem_bytes);

    int nsm = 148;
    cudaDeviceGetAttribute(&nsm, cudaDevAttrMultiProcessorCount, 0);

    main_kernel<<<nsm, NTHREADS, smem_bytes>>>(prec, msk, We, be, Wq, Wk, Wv, Wo, bo,
                                               g1, lb1, W1, b1, W2, b2, g2, lb2, out);
}